// round 1
// baseline (speedup 1.0000x reference)
#include <cuda_runtime.h>
#include <cstdint>
#include <cstddef>

// Problem constants
#define TT   100
#define BB   1024
#define NHD  128
#define NGATE 512
#define NIC  268
#define NBOT 256
#define NPC  256
#define NHDC 12

#define NBLK_REC 128   // persistent blocks for recurrence (must be <= SM count)

// ---------------------------------------------------------------------------
// scratch (no cudaMalloc allowed): h0/c0 + grid barrier state
// ---------------------------------------------------------------------------
__device__ float g_h0[BB * NHD];
__device__ float g_c0[BB * NHD];
__device__ unsigned g_count = 0;
__device__ volatile unsigned g_gen = 0;

__device__ __forceinline__ float sigm(float v) {
    return 1.0f / (1.0f + __expf(-v));
}

// ---------------------------------------------------------------------------
// Generic fp32 tiled GEMM: C[M,N] = A[M,K] @ W[K,N] (+ bias)
// block tile 64x64, K-chunk 16, 256 threads, 4x4 per thread.
// Requires M % 64 == 0 (true for all uses: 1024, 102400).
// ---------------------------------------------------------------------------
__global__ void gemm_kernel(const float* __restrict__ A,
                            const float* __restrict__ W,
                            const float* __restrict__ bias,
                            float* __restrict__ C,
                            int M, int N, int K)
{
    __shared__ float As[16][68];   // [k][m], padded (2-way max conflicts)
    __shared__ float Ws[16][68];   // [k][n], padded (row stride 272B, 16B aligned)

    const int tid = threadIdx.x;
    const int tx = tid & 15;        // N dim
    const int ty = tid >> 4;        // M dim
    const int n0 = blockIdx.x * 64;
    const int m0 = blockIdx.y * 64;

    float acc[4][4];
#pragma unroll
    for (int r = 0; r < 4; r++)
#pragma unroll
        for (int q = 0; q < 4; q++) acc[r][q] = 0.0f;

    for (int k0 = 0; k0 < K; k0 += 16) {
        // A tile: 64 rows x 16 k  (coalesced 64B segments)
        {
            const int k = tid & 15;
            const int m = tid >> 4;
#pragma unroll
            for (int p = 0; p < 4; p++) {
                const int mm = m + p * 16;
                float v = 0.0f;
                if (k0 + k < K) v = A[(size_t)(m0 + mm) * K + (k0 + k)];
                As[k][mm] = v;
            }
        }
        // W tile: 16 k x 64 n (coalesced)
        {
            const int n = tid & 63;
            const int kb = tid >> 6;
#pragma unroll
            for (int p = 0; p < 4; p++) {
                const int kk = kb + p * 4;
                float v = 0.0f;
                if ((k0 + kk < K) && (n0 + n < N)) v = W[(size_t)(k0 + kk) * N + (n0 + n)];
                Ws[kk][n] = v;
            }
        }
        __syncthreads();

#pragma unroll
        for (int kk = 0; kk < 16; kk++) {
            const float4 a4 = *(const float4*)&As[kk][ty * 4];
            const float4 b4 = *(const float4*)&Ws[kk][tx * 4];
            const float av[4] = {a4.x, a4.y, a4.z, a4.w};
            const float bv[4] = {b4.x, b4.y, b4.z, b4.w};
#pragma unroll
            for (int r = 0; r < 4; r++)
#pragma unroll
                for (int q = 0; q < 4; q++)
                    acc[r][q] = fmaf(av[r], bv[q], acc[r][q]);
        }
        __syncthreads();
    }

#pragma unroll
    for (int r = 0; r < 4; r++) {
        const int m = m0 + ty * 4 + r;
#pragma unroll
        for (int q = 0; q < 4; q++) {
            const int n = n0 + tx * 4 + q;
            if (n < N) {
                float v = acc[r][q];
                if (bias) v += bias[n];
                C[(size_t)m * N + n] = v;
            }
        }
    }
}

// ---------------------------------------------------------------------------
// Persistent LSTM recurrence.
// Grid = 128 blocks (16 row-tiles x 8 unit-groups), 256 threads each.
// Block owns rows [r0, r0+64) and hidden units [hu0, hu0+16).
// Per step: gates = [x_t, h_{t-1}] @ rnn_w + rnn_b for owned (row, unit, gate),
// elementwise LSTM update; h_t/c_t written straight into output hs/cs regions.
// c stays in registers for the whole kernel. Grid barrier between steps.
// ---------------------------------------------------------------------------
__global__ void lstm_kernel(const float* __restrict__ x,      // [T,B,3]
                            const float* __restrict__ rnn_w,  // [131,512]
                            const float* __restrict__ rnn_b,  // [512]
                            float* __restrict__ hs,           // [T,B,128]
                            float* __restrict__ cs)           // [T,B,128]
{
    extern __shared__ float sm[];
    float* wh_s = sm;                    // [128][64]  gate weights, [k][u*4+q]
    float* h_s  = sm + 128 * 64;         // [64][128]  h tile (natural layout)
    float* wx_s = h_s + 64 * 128;        // [3][64]
    float* b_s  = wx_s + 3 * 64;         // [64]
    float* x_s  = b_s + 64;              // [64][4]

    const int tid = threadIdx.x;
    const int tx = tid & 15;             // hidden unit within group
    const int ty = tid >> 4;             // row group (4 rows)
    const int cg = blockIdx.x & 7;       // unit group 0..7
    const int rt = blockIdx.x >> 3;      // row tile 0..15
    const int r0 = rt * 64;
    const int hu0 = cg * 16;

    // Load gate weights once (gate-interleaved: column c = u*4 + q, q in {i,j,f,o})
    for (int idx = tid; idx < 128 * 64; idx += 256) {
        const int k = idx >> 6;
        const int c = idx & 63;
        const int u = c >> 2, q = c & 3;
        wh_s[idx] = rnn_w[(size_t)(3 + k) * NGATE + q * NHD + hu0 + u];
    }
    if (tid < 192) {
        const int m = tid >> 6;
        const int c = tid & 63;
        const int u = c >> 2, q = c & 3;
        wx_s[m * 64 + c] = rnn_w[(size_t)m * NGATE + q * NHD + hu0 + u];
    }
    if (tid < 64) {
        const int u = tid >> 2, q = tid & 3;
        b_s[tid] = rnn_b[q * NHD + hu0 + u];
    }

    // c state lives in registers: thread owns rows r0+ty*4+r, unit hu0+tx
    float creg[4];
#pragma unroll
    for (int r = 0; r < 4; r++)
        creg[r] = g_c0[(size_t)(r0 + ty * 4 + r) * NHD + hu0 + tx];

    const float* hprev = g_h0;

    for (int t = 0; t < TT; t++) {
        // h tile load: 64x128 floats, coalesced float4
        for (int i = tid; i < 64 * 32; i += 256) {
            const int row = i >> 5;
            const int c4 = i & 31;
            *(float4*)&h_s[row * 128 + c4 * 4] =
                *(const float4*)&hprev[(size_t)(r0 + row) * NHD + c4 * 4];
        }
        if (tid < 64) {
            const float* xp = x + ((size_t)t * BB + r0 + tid) * 3;
            x_s[tid * 4 + 0] = xp[0];
            x_s[tid * 4 + 1] = xp[1];
            x_s[tid * 4 + 2] = xp[2];
        }
        __syncthreads();

        float acc[4][4];
#pragma unroll
        for (int r = 0; r < 4; r++) {
            const float x0 = x_s[(ty * 4 + r) * 4 + 0];
            const float x1 = x_s[(ty * 4 + r) * 4 + 1];
            const float x2 = x_s[(ty * 4 + r) * 4 + 2];
#pragma unroll
            for (int q = 0; q < 4; q++) {
                const int c = tx * 4 + q;
                float v = b_s[c];
                v = fmaf(x0, wx_s[0 * 64 + c], v);
                v = fmaf(x1, wx_s[1 * 64 + c], v);
                v = fmaf(x2, wx_s[2 * 64 + c], v);
                acc[r][q] = v;
            }
        }

        // K = 128 reduction, step 4: vectorized LDS, 64 FMA per thread per step
#pragma unroll 4
        for (int k = 0; k < 128; k += 4) {
            const float4 w0 = *(const float4*)&wh_s[(k + 0) * 64 + tx * 4];
            const float4 w1 = *(const float4*)&wh_s[(k + 1) * 64 + tx * 4];
            const float4 w2 = *(const float4*)&wh_s[(k + 2) * 64 + tx * 4];
            const float4 w3 = *(const float4*)&wh_s[(k + 3) * 64 + tx * 4];
#pragma unroll
            for (int r = 0; r < 4; r++) {
                const float4 hv = *(const float4*)&h_s[(ty * 4 + r) * 128 + k];
                acc[r][0] = fmaf(hv.x, w0.x, acc[r][0]);
                acc[r][1] = fmaf(hv.x, w0.y, acc[r][1]);
                acc[r][2] = fmaf(hv.x, w0.z, acc[r][2]);
                acc[r][3] = fmaf(hv.x, w0.w, acc[r][3]);
                acc[r][0] = fmaf(hv.y, w1.x, acc[r][0]);
                acc[r][1] = fmaf(hv.y, w1.y, acc[r][1]);
                acc[r][2] = fmaf(hv.y, w1.z, acc[r][2]);
                acc[r][3] = fmaf(hv.y, w1.w, acc[r][3]);
                acc[r][0] = fmaf(hv.z, w2.x, acc[r][0]);
                acc[r][1] = fmaf(hv.z, w2.y, acc[r][1]);
                acc[r][2] = fmaf(hv.z, w2.z, acc[r][2]);
                acc[r][3] = fmaf(hv.z, w2.w, acc[r][3]);
                acc[r][0] = fmaf(hv.w, w3.x, acc[r][0]);
                acc[r][1] = fmaf(hv.w, w3.y, acc[r][1]);
                acc[r][2] = fmaf(hv.w, w3.z, acc[r][2]);
                acc[r][3] = fmaf(hv.w, w3.w, acc[r][3]);
            }
        }

        // elementwise LSTM update (q: 0=i, 1=j, 2=f, 3=o)
#pragma unroll
        for (int r = 0; r < 4; r++) {
            const float c_new = creg[r] * sigm(acc[r][2] + 1.0f)
                              + sigm(acc[r][0]) * tanhf(acc[r][1]);
            const float h_new = tanhf(c_new) * sigm(acc[r][3]);
            creg[r] = c_new;
            const size_t off = ((size_t)t * BB + r0 + ty * 4 + r) * NHD + hu0 + tx;
            hs[off] = h_new;
            cs[off] = c_new;
        }

        // ---- grid barrier: h_t must be globally visible before next step ----
        __threadfence();
        __syncthreads();
        if (tid == 0) {
            const unsigned gen = g_gen;
            if (atomicAdd(&g_count, 1u) == NBLK_REC - 1u) {
                g_count = 0u;
                __threadfence();
                g_gen = gen + 1u;
            } else {
                while (g_gen == gen) { }
            }
        }
        __syncthreads();

        hprev = hs + (size_t)t * BB * NHD;
    }
}

// ---------------------------------------------------------------------------
// launch
// ---------------------------------------------------------------------------
#define LSTM_SMEM ((128 * 64 + 64 * 128 + 3 * 64 + 64 + 64 * 4) * 4)  // 67584 B

extern "C" void kernel_launch(void* const* d_in, const int* in_sizes, int n_in,
                              void* d_out, int out_size)
{
    const float* x       = (const float*)d_in[0];   // [100,1024,3]
    const float* init    = (const float*)d_in[1];   // [1024,268]
    const float* rnn_w   = (const float*)d_in[2];   // [131,512]
    const float* rnn_b   = (const float*)d_in[3];   // [512]
    const float* state_w = (const float*)d_in[4];   // [268,128]
    const float* state_b = (const float*)d_in[5];   // [128]
    const float* cell_w  = (const float*)d_in[6];   // [268,128]
    const float* cell_b  = (const float*)d_in[7];   // [128]
    const float* bneck_w = (const float*)d_in[8];   // [128,256]
    const float* pc_w    = (const float*)d_in[9];   // [256,256]
    const float* pc_b    = (const float*)d_in[10];  // [256]
    const float* hd_w    = (const float*)d_in[11];  // [256,12]
    const float* hd_b    = (const float*)d_in[12];  // [12]

    float* out = (float*)d_out;
    // output layout: hd [T,B,12] | pc [T,B,256] | bn [T,B,256] | hs [T,B,128] | cs [T,B,128]
    float* hd_out = out;
    float* pc_out = hd_out + (size_t)TT * BB * NHDC;
    float* bn_out = pc_out + (size_t)TT * BB * NPC;
    float* hs_out = bn_out + (size_t)TT * BB * NBOT;
    float* cs_out = hs_out + (size_t)TT * BB * NHD;

    float *h0p = nullptr, *c0p = nullptr;
    cudaGetSymbolAddress((void**)&h0p, g_h0);
    cudaGetSymbolAddress((void**)&c0p, g_c0);

    cudaFuncSetAttribute(lstm_kernel,
                         cudaFuncAttributeMaxDynamicSharedMemorySize, LSTM_SMEM);

    const dim3 thr(256);
    const int TB = TT * BB;  // 102400

    // h0 = init @ state_w + state_b ; c0 = init @ cell_w + cell_b   [1024x128, K=268]
    gemm_kernel<<<dim3(2, 16), thr>>>(init, state_w, state_b, h0p, BB, NHD, NIC);
    gemm_kernel<<<dim3(2, 16), thr>>>(init, cell_w,  cell_b,  c0p, BB, NHD, NIC);

    // recurrence -> hs, cs
    lstm_kernel<<<NBLK_REC, 256, LSTM_SMEM>>>(x, rnn_w, rnn_b, hs_out, cs_out);

    // batched readouts over all T*B rows
    gemm_kernel<<<dim3(4, TB / 64), thr>>>(hs_out, bneck_w, nullptr, bn_out, TB, NBOT, NHD);
    gemm_kernel<<<dim3(4, TB / 64), thr>>>(bn_out, pc_w, pc_b, pc_out, TB, NPC, NBOT);
    gemm_kernel<<<dim3(1, TB / 64), thr>>>(bn_out, hd_w, hd_b, hd_out, TB, NHDC, NBOT);
}

// round 3
// speedup vs baseline: 1.0393x; 1.0393x over previous
#include <cuda_runtime.h>
#include <cuda_bf16.h>
#include <cstdint>
#include <cstddef>

// Problem constants
#define TT   100
#define BB   1024
#define NHD  128
#define NGATE 512
#define NIC  268
#define NBOT 256
#define NPC  256
#define NHDC 12
#define TB   (TT * BB)   // 102400

#define NBLK_REC 128

// ---------------------------------------------------------------------------
// scratch: h0/c0 + grid barrier state
// ---------------------------------------------------------------------------
__device__ float g_h0[BB * NHD];
__device__ float g_c0[BB * NHD];
__device__ unsigned g_count = 0;
__device__ volatile unsigned g_gen = 0;

__device__ __forceinline__ float sigm(float v) {
    return 1.0f / (1.0f + __expf(-v));
}

__device__ __forceinline__ uint32_t smem_u32(const void* p) {
    uint32_t a;
    asm("{ .reg .u64 t; cvta.to.shared.u64 t, %1; cvt.u32.u64 %0, t; }"
        : "=r"(a) : "l"(p));
    return a;
}

// ldmatrix helpers (sm_75+, fine on base sm_103 target)
__device__ __forceinline__ void ldsm_x4(uint32_t& r0, uint32_t& r1, uint32_t& r2,
                                        uint32_t& r3, uint32_t addr) {
    asm volatile("ldmatrix.sync.aligned.m8n8.x4.shared.b16 {%0,%1,%2,%3}, [%4];"
                 : "=r"(r0), "=r"(r1), "=r"(r2), "=r"(r3) : "r"(addr));
}
__device__ __forceinline__ void ldsm_x4_t(uint32_t& r0, uint32_t& r1, uint32_t& r2,
                                          uint32_t& r3, uint32_t addr) {
    asm volatile("ldmatrix.sync.aligned.m8n8.x4.trans.shared.b16 {%0,%1,%2,%3}, [%4];"
                 : "=r"(r0), "=r"(r1), "=r"(r2), "=r"(r3) : "r"(addr));
}
// HMMA m16n8k16 bf16 -> fp32
__device__ __forceinline__ void mma16816(float* d, const uint32_t* a, const uint32_t* b) {
    asm volatile(
        "mma.sync.aligned.m16n8k16.row.col.f32.bf16.bf16.f32 "
        "{%0,%1,%2,%3}, {%4,%5,%6,%7}, {%8,%9}, {%0,%1,%2,%3};"
        : "+f"(d[0]), "+f"(d[1]), "+f"(d[2]), "+f"(d[3])
        : "r"(a[0]), "r"(a[1]), "r"(a[2]), "r"(a[3]), "r"(b[0]), "r"(b[1]));
}

__device__ __forceinline__ void split2(float v, __nv_bfloat16& hi, __nv_bfloat16& lo) {
    hi = __float2bfloat16(v);
    lo = __float2bfloat16(v - __bfloat162float(hi));
}

// ---------------------------------------------------------------------------
// Small fp32 GEMM for h0/c0 init
// ---------------------------------------------------------------------------
__global__ void gemm_kernel(const float* __restrict__ A, const float* __restrict__ W,
                            const float* __restrict__ bias, float* __restrict__ C,
                            int M, int N, int K)
{
    __shared__ float As[16][68];
    __shared__ float Ws[16][68];
    const int tid = threadIdx.x;
    const int tx = tid & 15, ty = tid >> 4;
    const int n0 = blockIdx.x * 64, m0 = blockIdx.y * 64;

    float acc[4][4];
#pragma unroll
    for (int r = 0; r < 4; r++)
#pragma unroll
        for (int q = 0; q < 4; q++) acc[r][q] = 0.0f;

    for (int k0 = 0; k0 < K; k0 += 16) {
        {
            const int k = tid & 15, m = tid >> 4;
#pragma unroll
            for (int p = 0; p < 4; p++) {
                const int mm = m + p * 16;
                float v = 0.0f;
                if (k0 + k < K) v = A[(size_t)(m0 + mm) * K + (k0 + k)];
                As[k][mm] = v;
            }
        }
        {
            const int n = tid & 63, kb = tid >> 6;
#pragma unroll
            for (int p = 0; p < 4; p++) {
                const int kk = kb + p * 4;
                float v = 0.0f;
                if ((k0 + kk < K) && (n0 + n < N)) v = W[(size_t)(k0 + kk) * N + (n0 + n)];
                Ws[kk][n] = v;
            }
        }
        __syncthreads();
#pragma unroll
        for (int kk = 0; kk < 16; kk++) {
            const float4 a4 = *(const float4*)&As[kk][ty * 4];
            const float4 b4 = *(const float4*)&Ws[kk][tx * 4];
            const float av[4] = {a4.x, a4.y, a4.z, a4.w};
            const float bv[4] = {b4.x, b4.y, b4.z, b4.w};
#pragma unroll
            for (int r = 0; r < 4; r++)
#pragma unroll
                for (int q = 0; q < 4; q++)
                    acc[r][q] = fmaf(av[r], bv[q], acc[r][q]);
        }
        __syncthreads();
    }
#pragma unroll
    for (int r = 0; r < 4; r++) {
        const int m = m0 + ty * 4 + r;
#pragma unroll
        for (int q = 0; q < 4; q++) {
            const int n = n0 + tx * 4 + q;
            if (n < N) {
                float v = acc[r][q];
                if (bias) v += bias[n];
                C[(size_t)m * N + n] = v;
            }
        }
    }
}

// ---------------------------------------------------------------------------
// Persistent LSTM recurrence — 512 threads/block, 128 blocks, grid barrier.
// ---------------------------------------------------------------------------
__global__ void __launch_bounds__(512, 1)
lstm_kernel(const float* __restrict__ x,      // [T,B,3]
            const float* __restrict__ rnn_w,  // [131,512]
            const float* __restrict__ rnn_b,  // [512]
            float* __restrict__ hs,           // [T,B,128]
            float* __restrict__ cs)           // [T,B,128]
{
    extern __shared__ float sm[];
    float* wh_s = sm;              // [128][64]
    float* h_s  = sm + 8192;       // [64][128]
    float* wx_s = h_s + 8192;      // [3][64]
    float* b_s  = wx_s + 192;      // [64]
    float* x_s  = b_s + 64;        // [64][4]

    const int tid = threadIdx.x;
    const int tx = tid & 15;       // gate-col group (unit)
    const int ty = tid >> 4;       // 0..31, rows ty*2, ty*2+1
    const int cg = blockIdx.x & 7;
    const int rt = blockIdx.x >> 3;
    const int r0 = rt * 64;
    const int hu0 = cg * 16;

    for (int idx = tid; idx < 128 * 64; idx += 512) {
        const int k = idx >> 6, c = idx & 63;
        const int u = c >> 2, q = c & 3;
        wh_s[idx] = rnn_w[(size_t)(3 + k) * NGATE + q * NHD + hu0 + u];
    }
    if (tid < 192) {
        const int m = tid >> 6, c = tid & 63;
        const int u = c >> 2, q = c & 3;
        wx_s[m * 64 + c] = rnn_w[(size_t)m * NGATE + q * NHD + hu0 + u];
    }
    if (tid < 64) {
        const int u = tid >> 2, q = tid & 3;
        b_s[tid] = rnn_b[q * NHD + hu0 + u];
    }

    float creg[2];
#pragma unroll
    for (int r = 0; r < 2; r++)
        creg[r] = g_c0[(size_t)(r0 + ty * 2 + r) * NHD + hu0 + tx];

    const float* hprev = g_h0;

    for (int t = 0; t < TT; t++) {
        for (int i = tid; i < 64 * 32; i += 512) {
            const int row = i >> 5, c4 = i & 31;
            *(float4*)&h_s[row * 128 + c4 * 4] =
                *(const float4*)&hprev[(size_t)(r0 + row) * NHD + c4 * 4];
        }
        if (tid < 64) {
            const float* xp = x + ((size_t)t * BB + r0 + tid) * 3;
            x_s[tid * 4 + 0] = xp[0];
            x_s[tid * 4 + 1] = xp[1];
            x_s[tid * 4 + 2] = xp[2];
        }
        __syncthreads();

        float acc[2][4];
#pragma unroll
        for (int r = 0; r < 2; r++) {
            const float x0 = x_s[(ty * 2 + r) * 4 + 0];
            const float x1 = x_s[(ty * 2 + r) * 4 + 1];
            const float x2 = x_s[(ty * 2 + r) * 4 + 2];
#pragma unroll
            for (int q = 0; q < 4; q++) {
                const int c = tx * 4 + q;
                float v = b_s[c];
                v = fmaf(x0, wx_s[0 * 64 + c], v);
                v = fmaf(x1, wx_s[1 * 64 + c], v);
                v = fmaf(x2, wx_s[2 * 64 + c], v);
                acc[r][q] = v;
            }
        }

#pragma unroll 4
        for (int k = 0; k < 128; k += 4) {
            const float4 w0 = *(const float4*)&wh_s[(k + 0) * 64 + tx * 4];
            const float4 w1 = *(const float4*)&wh_s[(k + 1) * 64 + tx * 4];
            const float4 w2 = *(const float4*)&wh_s[(k + 2) * 64 + tx * 4];
            const float4 w3 = *(const float4*)&wh_s[(k + 3) * 64 + tx * 4];
#pragma unroll
            for (int r = 0; r < 2; r++) {
                const float4 hv = *(const float4*)&h_s[(ty * 2 + r) * 128 + k];
                acc[r][0] = fmaf(hv.x, w0.x, acc[r][0]);
                acc[r][1] = fmaf(hv.x, w0.y, acc[r][1]);
                acc[r][2] = fmaf(hv.x, w0.z, acc[r][2]);
                acc[r][3] = fmaf(hv.x, w0.w, acc[r][3]);
                acc[r][0] = fmaf(hv.y, w1.x, acc[r][0]);
                acc[r][1] = fmaf(hv.y, w1.y, acc[r][1]);
                acc[r][2] = fmaf(hv.y, w1.z, acc[r][2]);
                acc[r][3] = fmaf(hv.y, w1.w, acc[r][3]);
                acc[r][0] = fmaf(hv.z, w2.x, acc[r][0]);
                acc[r][1] = fmaf(hv.z, w2.y, acc[r][1]);
                acc[r][2] = fmaf(hv.z, w2.z, acc[r][2]);
                acc[r][3] = fmaf(hv.z, w2.w, acc[r][3]);
                acc[r][0] = fmaf(hv.w, w3.x, acc[r][0]);
                acc[r][1] = fmaf(hv.w, w3.y, acc[r][1]);
                acc[r][2] = fmaf(hv.w, w3.z, acc[r][2]);
                acc[r][3] = fmaf(hv.w, w3.w, acc[r][3]);
            }
        }

#pragma unroll
        for (int r = 0; r < 2; r++) {
            const float c_new = creg[r] * sigm(acc[r][2] + 1.0f)
                              + sigm(acc[r][0]) * tanhf(acc[r][1]);
            const float h_new = tanhf(c_new) * sigm(acc[r][3]);
            creg[r] = c_new;
            const size_t off = ((size_t)t * BB + r0 + ty * 2 + r) * NHD + hu0 + tx;
            hs[off] = h_new;
            cs[off] = c_new;
        }

        __threadfence();
        __syncthreads();
        if (tid == 0) {
            const unsigned gen = g_gen;
            if (atomicAdd(&g_count, 1u) == NBLK_REC - 1u) {
                g_count = 0u;
                __threadfence();
                g_gen = gen + 1u;
            } else {
                while (g_gen == gen) { }
            }
        }
        __syncthreads();

        hprev = hs + (size_t)t * BB * NHD;
    }
}

// ---------------------------------------------------------------------------
// Fused readout on HMMA (mma.sync bf16, split-2 for fp32-grade precision):
//   bn = hs @ bneck_w ; pc = bn @ pc_w + pc_b ; hd = bn @ hd_w + hd_b
// One block per 128 rows, 256 threads (8 warps).
// Warp grid: wm = wid&1 (two 64-row halves), wn = wid>>1 (4 N-tiles).
// ---------------------------------------------------------------------------
// smem byte offsets (phase 1 regions die before phase 2 regions are written)
#define RA_HI   0u         // hs  [128][136] bf16  (stride 272B: conflict-free ldsm)
#define RA_LO   34816u
#define RB_HI   69632u     // bneck chunk [128][136] bf16
#define RB_LO   104448u
#define RA2_HI  0u         // bn  [128][264] bf16   (overlaps RA/RB after bn done)
#define RA2_LO  67584u
#define RB2_HI  139264u    // pc/hd weight chunk [256][72] bf16
#define RB2_LO  176128u
#define RO_SMEM 212992u
#define SA   136
#define SA2  264
#define SB2  72

__global__ void __launch_bounds__(256, 1)
readout_kernel(const float* __restrict__ hs,      // [TB,128]
               const float* __restrict__ bneck_w, // [128,256]
               const float* __restrict__ pc_w,    // [256,256]
               const float* __restrict__ pc_b,    // [256]
               const float* __restrict__ hd_w,    // [256,12]
               const float* __restrict__ hd_b,    // [12]
               float* __restrict__ bn_out,        // [TB,256]
               float* __restrict__ pc_out,        // [TB,256]
               float* __restrict__ hd_out)        // [TB,12]
{
    extern __shared__ __align__(16) char dsm[];
    const uint32_t base_u = smem_u32(dsm);
    const int tid  = threadIdx.x;
    const int wid  = tid >> 5, lane = tid & 31;
    const int wm   = wid & 1,  wn   = wid >> 1;
    const int g    = lane >> 2, tg2 = (lane & 3) * 2;
    const int lr   = lane & 15, lc8 = (lane >> 4) << 3;
    const int m0   = blockIdx.x * 128;

    // ---- stage A = hs tile, split bf16 hi/lo ----
    {
        const float* hrow = hs + (size_t)m0 * 128;
        for (int i = tid; i < 128 * 128; i += 256) {
            const int row = i >> 7, k = i & 127;
            __nv_bfloat16 hi, lo;
            split2(hrow[i], hi, lo);
            *(__nv_bfloat16*)(dsm + RA_HI + 2 * (row * SA + k)) = hi;
            *(__nv_bfloat16*)(dsm + RA_LO + 2 * (row * SA + k)) = lo;
        }
    }

    float acc[2][4][4][4];
#pragma unroll
    for (int a = 0; a < 2; a++)
#pragma unroll
        for (int b = 0; b < 4; b++)
#pragma unroll
            for (int c = 0; c < 4; c++)
#pragma unroll
                for (int d = 0; d < 4; d++) acc[a][b][c][d] = 0.0f;

    // ---- bn GEMM: two N-halves of 128, K=128 ----
#pragma unroll 1
    for (int nh = 0; nh < 2; nh++) {
        __syncthreads();   // A staged (nh=0) / previous-half MMAs done (nh=1)
        for (int i = tid; i < 128 * 128; i += 256) {
            const int k = i >> 7, n = i & 127;
            __nv_bfloat16 hi, lo;
            split2(bneck_w[(size_t)k * 256 + nh * 128 + n], hi, lo);
            *(__nv_bfloat16*)(dsm + RB_HI + 2 * (k * SA + n)) = hi;
            *(__nv_bfloat16*)(dsm + RB_LO + 2 * (k * SA + n)) = lo;
        }
        __syncthreads();

#pragma unroll
        for (int ks = 0; ks < 8; ks++) {
            const int k = ks * 16;
            uint32_t bh[4][2], bl[4][2];
#pragma unroll
            for (int p = 0; p < 2; p++) {
                const uint32_t off = 2 * ((k + lr) * SA + wn * 32 + p * 16 + lc8);
                ldsm_x4_t(bh[2*p][0], bh[2*p][1], bh[2*p+1][0], bh[2*p+1][1],
                          base_u + RB_HI + off);
                ldsm_x4_t(bl[2*p][0], bl[2*p][1], bl[2*p+1][0], bl[2*p+1][1],
                          base_u + RB_LO + off);
            }
#pragma unroll
            for (int mi = 0; mi < 4; mi++) {
                uint32_t ah[4], al[4];
                const uint32_t aoff = 2 * ((wm * 64 + mi * 16 + lr) * SA + k + lc8);
                ldsm_x4(ah[0], ah[1], ah[2], ah[3], base_u + RA_HI + aoff);
                ldsm_x4(al[0], al[1], al[2], al[3], base_u + RA_LO + aoff);
#pragma unroll
                for (int ni = 0; ni < 4; ni++) {
                    mma16816(acc[nh][mi][ni], ah, bh[ni]);
                    mma16816(acc[nh][mi][ni], ah, bl[ni]);
                    mma16816(acc[nh][mi][ni], al, bh[ni]);
                }
            }
        }
    }
    __syncthreads();   // all bn MMAs done: A/B regions dead, safe to write A2

    // ---- bn epilogue: global store + re-split into A2 (pc's A operand) ----
#pragma unroll
    for (int nh = 0; nh < 2; nh++)
#pragma unroll
    for (int mi = 0; mi < 4; mi++)
#pragma unroll
    for (int ni = 0; ni < 4; ni++) {
        const int r0  = wm * 64 + mi * 16 + g;
        const int col = nh * 128 + wn * 32 + ni * 8 + tg2;
        const float* a4 = acc[nh][mi][ni];
        *(float2*)&bn_out[(size_t)(m0 + r0) * 256 + col]     = make_float2(a4[0], a4[1]);
        *(float2*)&bn_out[(size_t)(m0 + r0 + 8) * 256 + col] = make_float2(a4[2], a4[3]);

        __nv_bfloat16 h0, l0, h1, l1;
        split2(a4[0], h0, l0); split2(a4[1], h1, l1);
        __nv_bfloat162 ph, pl;
        ph.x = h0; ph.y = h1; pl.x = l0; pl.y = l1;
        *(__nv_bfloat162*)(dsm + RA2_HI + 2 * (r0 * SA2 + col)) = ph;
        *(__nv_bfloat162*)(dsm + RA2_LO + 2 * (r0 * SA2 + col)) = pl;
        split2(a4[2], h0, l0); split2(a4[3], h1, l1);
        ph.x = h0; ph.y = h1; pl.x = l0; pl.y = l1;
        *(__nv_bfloat162*)(dsm + RA2_HI + 2 * ((r0 + 8) * SA2 + col)) = ph;
        *(__nv_bfloat162*)(dsm + RA2_LO + 2 * ((r0 + 8) * SA2 + col)) = pl;
    }

    // ---- pc (4 chunks of N=64) + hd (chunk 4, N=16 padded), K=256 ----
#pragma unroll 1
    for (int c = 0; c < 5; c++) {
        __syncthreads();   // A2 writes done (c=0) / previous chunk MMAs done
        if (c < 4) {
            for (int i = tid; i < 256 * 64; i += 256) {
                const int k = i >> 6, n = i & 63;
                __nv_bfloat16 hi, lo;
                split2(pc_w[(size_t)k * 256 + c * 64 + n], hi, lo);
                *(__nv_bfloat16*)(dsm + RB2_HI + 2 * (k * SB2 + n)) = hi;
                *(__nv_bfloat16*)(dsm + RB2_LO + 2 * (k * SB2 + n)) = lo;
            }
        } else {
            for (int i = tid; i < 256 * 16; i += 256) {
                const int k = i >> 4, n = i & 15;
                const float v = (n < 12) ? hd_w[(size_t)k * 12 + n] : 0.0f;
                __nv_bfloat16 hi, lo;
                split2(v, hi, lo);
                *(__nv_bfloat16*)(dsm + RB2_HI + 2 * (k * SB2 + n)) = hi;
                *(__nv_bfloat16*)(dsm + RB2_LO + 2 * (k * SB2 + n)) = lo;
            }
        }
        __syncthreads();

        if (c < 4) {
            float acc2[4][2][4];
#pragma unroll
            for (int a = 0; a < 4; a++)
#pragma unroll
                for (int b = 0; b < 2; b++)
#pragma unroll
                    for (int e = 0; e < 4; e++) acc2[a][b][e] = 0.0f;

#pragma unroll
            for (int ks = 0; ks < 16; ks++) {
                const int k = ks * 16;
                uint32_t bh[2][2], bl[2][2];
                const uint32_t boff = 2 * ((k + lr) * SB2 + wn * 16 + lc8);
                ldsm_x4_t(bh[0][0], bh[0][1], bh[1][0], bh[1][1], base_u + RB2_HI + boff);
                ldsm_x4_t(bl[0][0], bl[0][1], bl[1][0], bl[1][1], base_u + RB2_LO + boff);
#pragma unroll
                for (int mi = 0; mi < 4; mi++) {
                    uint32_t ah[4], al[4];
                    const uint32_t aoff = 2 * ((wm * 64 + mi * 16 + lr) * SA2 + k + lc8);
                    ldsm_x4(ah[0], ah[1], ah[2], ah[3], base_u + RA2_HI + aoff);
                    ldsm_x4(al[0], al[1], al[2], al[3], base_u + RA2_LO + aoff);
#pragma unroll
                    for (int ni = 0; ni < 2; ni++) {
                        mma16816(acc2[mi][ni], ah, bh[ni]);
                        mma16816(acc2[mi][ni], ah, bl[ni]);
                        mma16816(acc2[mi][ni], al, bh[ni]);
                    }
                }
            }
#pragma unroll
            for (int mi = 0; mi < 4; mi++)
#pragma unroll
            for (int ni = 0; ni < 2; ni++) {
                const int r0  = wm * 64 + mi * 16 + g;
                const int col = c * 64 + wn * 16 + ni * 8 + tg2;
                const float b0 = __ldg(&pc_b[col]), b1 = __ldg(&pc_b[col + 1]);
                const float* a4 = acc2[mi][ni];
                *(float2*)&pc_out[(size_t)(m0 + r0) * 256 + col] =
                    make_float2(a4[0] + b0, a4[1] + b1);
                *(float2*)&pc_out[(size_t)(m0 + r0 + 8) * 256 + col] =
                    make_float2(a4[2] + b0, a4[3] + b1);
            }
        } else if (wid < 2) {
            // hd: warps 0,1 handle M halves; N=16 (12 real)
            float acc3[4][2][4];
#pragma unroll
            for (int a = 0; a < 4; a++)
#pragma unroll
                for (int b = 0; b < 2; b++)
#pragma unroll
                    for (int e = 0; e < 4; e++) acc3[a][b][e] = 0.0f;

#pragma unroll
            for (int ks = 0; ks < 16; ks++) {
                const int k = ks * 16;
                uint32_t bh[2][2], bl[2][2];
                const uint32_t boff = 2 * ((k + lr) * SB2 + lc8);
                ldsm_x4_t(bh[0][0], bh[0][1], bh[1][0], bh[1][1], base_u + RB2_HI + boff);
                ldsm_x4_t(bl[0][0], bl[0][1], bl[1][0], bl[1][1], base_u + RB2_LO + boff);
#pragma unroll
                for (int mi = 0; mi < 4; mi++) {
                    uint32_t ah[4], al[4];
                    const uint32_t aoff = 2 * ((wid * 64 + mi * 16 + lr) * SA2 + k + lc8);
                    ldsm_x4(ah[0], ah[1], ah[2], ah[3], base_u + RA2_HI + aoff);
                    ldsm_x4(al[0], al[1], al[2], al[3], base_u + RA2_LO + aoff);
#pragma unroll
                    for (int ni = 0; ni < 2; ni++) {
                        mma16816(acc3[mi][ni], ah, bh[ni]);
                        mma16816(acc3[mi][ni], ah, bl[ni]);
                        mma16816(acc3[mi][ni], al, bh[ni]);
                    }
                }
            }
#pragma unroll
            for (int mi = 0; mi < 4; mi++)
#pragma unroll
            for (int ni = 0; ni < 2; ni++) {
                const int col = ni * 8 + tg2;
                if (col < 12) {
                    const int r0 = wid * 64 + mi * 16 + g;
                    const float b0 = __ldg(&hd_b[col]), b1 = __ldg(&hd_b[col + 1]);
                    const float* a4 = acc3[mi][ni];
                    *(float2*)&hd_out[(size_t)(m0 + r0) * 12 + col] =
                        make_float2(a4[0] + b0, a4[1] + b1);
                    *(float2*)&hd_out[(size_t)(m0 + r0 + 8) * 12 + col] =
                        make_float2(a4[2] + b0, a4[3] + b1);
                }
            }
        }
    }
}

// ---------------------------------------------------------------------------
// launch
// ---------------------------------------------------------------------------
#define LSTM_SMEM ((128 * 64 + 64 * 128 + 3 * 64 + 64 + 64 * 4) * 4)

extern "C" void kernel_launch(void* const* d_in, const int* in_sizes, int n_in,
                              void* d_out, int out_size)
{
    const float* x       = (const float*)d_in[0];
    const float* init    = (const float*)d_in[1];
    const float* rnn_w   = (const float*)d_in[2];
    const float* rnn_b   = (const float*)d_in[3];
    const float* state_w = (const float*)d_in[4];
    const float* state_b = (const float*)d_in[5];
    const float* cell_w  = (const float*)d_in[6];
    const float* cell_b  = (const float*)d_in[7];
    const float* bneck_w = (const float*)d_in[8];
    const float* pc_w    = (const float*)d_in[9];
    const float* pc_b    = (const float*)d_in[10];
    const float* hd_w    = (const float*)d_in[11];
    const float* hd_b    = (const float*)d_in[12];

    float* out = (float*)d_out;
    float* hd_out = out;
    float* pc_out = hd_out + (size_t)TB * NHDC;
    float* bn_out = pc_out + (size_t)TB * NPC;
    float* hs_out = bn_out + (size_t)TB * NBOT;
    float* cs_out = hs_out + (size_t)TB * NHD;

    float *h0p = nullptr, *c0p = nullptr;
    cudaGetSymbolAddress((void**)&h0p, g_h0);
    cudaGetSymbolAddress((void**)&c0p, g_c0);

    cudaFuncSetAttribute(lstm_kernel,
                         cudaFuncAttributeMaxDynamicSharedMemorySize, LSTM_SMEM);
    cudaFuncSetAttribute(readout_kernel,
                         cudaFuncAttributeMaxDynamicSharedMemorySize, RO_SMEM);

    // h0 / c0
    gemm_kernel<<<dim3(2, 16), 256>>>(init, state_w, state_b, h0p, BB, NHD, NIC);
    gemm_kernel<<<dim3(2, 16), 256>>>(init, cell_w,  cell_b,  c0p, BB, NHD, NIC);

    // recurrence
    lstm_kernel<<<NBLK_REC, 512, LSTM_SMEM>>>(x, rnn_w, rnn_b, hs_out, cs_out);

    // fused tensor-core readout
    readout_kernel<<<TB / 128, 256, RO_SMEM>>>(hs_out, bneck_w, pc_w, pc_b,
                                               hd_w, hd_b, bn_out, pc_out, hd_out);
}

// round 4
// speedup vs baseline: 1.0398x; 1.0005x over previous
#include <cuda_runtime.h>
#include <cuda_bf16.h>
#include <cstdint>
#include <cstddef>

// Problem constants
#define TT   100
#define BB   1024
#define NHD  128
#define NGATE 512
#define NIC  268
#define NBOT 256
#define NPC  256
#define NHDC 12
#define TB   (TT * BB)   // 102400

#define NBLK_REC 128

// ---------------------------------------------------------------------------
// scratch: h0/c0 + grid barrier state
// ---------------------------------------------------------------------------
__device__ float g_h0[BB * NHD];
__device__ float g_c0[BB * NHD];
__device__ unsigned g_count = 0;
__device__ volatile unsigned g_gen = 0;

__device__ __forceinline__ float sigm(float v) {
    return 1.0f / (1.0f + __expf(-v));
}

__device__ __forceinline__ uint32_t smem_u32(const void* p) {
    uint32_t a;
    asm("{ .reg .u64 t; cvta.to.shared.u64 t, %1; cvt.u32.u64 %0, t; }"
        : "=r"(a) : "l"(p));
    return a;
}

// ldmatrix helpers (sm_75+, fine on base sm_103 target)
__device__ __forceinline__ void ldsm_x4(uint32_t& r0, uint32_t& r1, uint32_t& r2,
                                        uint32_t& r3, uint32_t addr) {
    asm volatile("ldmatrix.sync.aligned.m8n8.x4.shared.b16 {%0,%1,%2,%3}, [%4];"
                 : "=r"(r0), "=r"(r1), "=r"(r2), "=r"(r3) : "r"(addr));
}
__device__ __forceinline__ void ldsm_x4_t(uint32_t& r0, uint32_t& r1, uint32_t& r2,
                                          uint32_t& r3, uint32_t addr) {
    asm volatile("ldmatrix.sync.aligned.m8n8.x4.trans.shared.b16 {%0,%1,%2,%3}, [%4];"
                 : "=r"(r0), "=r"(r1), "=r"(r2), "=r"(r3) : "r"(addr));
}
// HMMA m16n8k16 bf16 -> fp32
__device__ __forceinline__ void mma16816(float* d, const uint32_t* a, const uint32_t* b) {
    asm volatile(
        "mma.sync.aligned.m16n8k16.row.col.f32.bf16.bf16.f32 "
        "{%0,%1,%2,%3}, {%4,%5,%6,%7}, {%8,%9}, {%0,%1,%2,%3};"
        : "+f"(d[0]), "+f"(d[1]), "+f"(d[2]), "+f"(d[3])
        : "r"(a[0]), "r"(a[1]), "r"(a[2]), "r"(a[3]), "r"(b[0]), "r"(b[1]));
}

__device__ __forceinline__ void split2(float v, __nv_bfloat16& hi, __nv_bfloat16& lo) {
    hi = __float2bfloat16(v);
    lo = __float2bfloat16(v - __bfloat162float(hi));
}

// ---------------------------------------------------------------------------
// Small fp32 GEMM for h0/c0 init
// ---------------------------------------------------------------------------
__global__ void gemm_kernel(const float* __restrict__ A, const float* __restrict__ W,
                            const float* __restrict__ bias, float* __restrict__ C,
                            int M, int N, int K)
{
    __shared__ float As[16][68];
    __shared__ float Ws[16][68];
    const int tid = threadIdx.x;
    const int tx = tid & 15, ty = tid >> 4;
    const int n0 = blockIdx.x * 64, m0 = blockIdx.y * 64;

    float acc[4][4];
#pragma unroll
    for (int r = 0; r < 4; r++)
#pragma unroll
        for (int q = 0; q < 4; q++) acc[r][q] = 0.0f;

    for (int k0 = 0; k0 < K; k0 += 16) {
        {
            const int k = tid & 15, m = tid >> 4;
#pragma unroll
            for (int p = 0; p < 4; p++) {
                const int mm = m + p * 16;
                float v = 0.0f;
                if (k0 + k < K) v = A[(size_t)(m0 + mm) * K + (k0 + k)];
                As[k][mm] = v;
            }
        }
        {
            const int n = tid & 63, kb = tid >> 6;
#pragma unroll
            for (int p = 0; p < 4; p++) {
                const int kk = kb + p * 4;
                float v = 0.0f;
                if ((k0 + kk < K) && (n0 + n < N)) v = W[(size_t)(k0 + kk) * N + (n0 + n)];
                Ws[kk][n] = v;
            }
        }
        __syncthreads();
#pragma unroll
        for (int kk = 0; kk < 16; kk++) {
            const float4 a4 = *(const float4*)&As[kk][ty * 4];
            const float4 b4 = *(const float4*)&Ws[kk][tx * 4];
            const float av[4] = {a4.x, a4.y, a4.z, a4.w};
            const float bv[4] = {b4.x, b4.y, b4.z, b4.w};
#pragma unroll
            for (int r = 0; r < 4; r++)
#pragma unroll
                for (int q = 0; q < 4; q++)
                    acc[r][q] = fmaf(av[r], bv[q], acc[r][q]);
        }
        __syncthreads();
    }
#pragma unroll
    for (int r = 0; r < 4; r++) {
        const int m = m0 + ty * 4 + r;
#pragma unroll
        for (int q = 0; q < 4; q++) {
            const int n = n0 + tx * 4 + q;
            if (n < N) {
                float v = acc[r][q];
                if (bias) v += bias[n];
                C[(size_t)m * N + n] = v;
            }
        }
    }
}

// ---------------------------------------------------------------------------
// Persistent LSTM recurrence — 512 threads/block, 128 blocks, grid barrier.
// ---------------------------------------------------------------------------
__global__ void __launch_bounds__(512, 1)
lstm_kernel(const float* __restrict__ x,      // [T,B,3]
            const float* __restrict__ rnn_w,  // [131,512]
            const float* __restrict__ rnn_b,  // [512]
            float* __restrict__ hs,           // [T,B,128]
            float* __restrict__ cs)           // [T,B,128]
{
    extern __shared__ float sm[];
    float* wh_s = sm;              // [128][64]
    float* h_s  = sm + 8192;       // [64][128]
    float* wx_s = h_s + 8192;      // [3][64]
    float* b_s  = wx_s + 192;      // [64]
    float* x_s  = b_s + 64;        // [64][4]

    const int tid = threadIdx.x;
    const int tx = tid & 15;       // gate-col group (unit)
    const int ty = tid >> 4;       // 0..31, rows ty*2, ty*2+1
    const int cg = blockIdx.x & 7;
    const int rt = blockIdx.x >> 3;
    const int r0 = rt * 64;
    const int hu0 = cg * 16;

    for (int idx = tid; idx < 128 * 64; idx += 512) {
        const int k = idx >> 6, c = idx & 63;
        const int u = c >> 2, q = c & 3;
        wh_s[idx] = rnn_w[(size_t)(3 + k) * NGATE + q * NHD + hu0 + u];
    }
    if (tid < 192) {
        const int m = tid >> 6, c = tid & 63;
        const int u = c >> 2, q = c & 3;
        wx_s[m * 64 + c] = rnn_w[(size_t)m * NGATE + q * NHD + hu0 + u];
    }
    if (tid < 64) {
        const int u = tid >> 2, q = tid & 3;
        b_s[tid] = rnn_b[q * NHD + hu0 + u];
    }

    float creg[2];
#pragma unroll
    for (int r = 0; r < 2; r++)
        creg[r] = g_c0[(size_t)(r0 + ty * 2 + r) * NHD + hu0 + tx];

    const float* hprev = g_h0;

    for (int t = 0; t < TT; t++) {
        for (int i = tid; i < 64 * 32; i += 512) {
            const int row = i >> 5, c4 = i & 31;
            *(float4*)&h_s[row * 128 + c4 * 4] =
                *(const float4*)&hprev[(size_t)(r0 + row) * NHD + c4 * 4];
        }
        if (tid < 64) {
            const float* xp = x + ((size_t)t * BB + r0 + tid) * 3;
            x_s[tid * 4 + 0] = xp[0];
            x_s[tid * 4 + 1] = xp[1];
            x_s[tid * 4 + 2] = xp[2];
        }
        __syncthreads();

        float acc[2][4];
#pragma unroll
        for (int r = 0; r < 2; r++) {
            const float x0 = x_s[(ty * 2 + r) * 4 + 0];
            const float x1 = x_s[(ty * 2 + r) * 4 + 1];
            const float x2 = x_s[(ty * 2 + r) * 4 + 2];
#pragma unroll
            for (int q = 0; q < 4; q++) {
                const int c = tx * 4 + q;
                float v = b_s[c];
                v = fmaf(x0, wx_s[0 * 64 + c], v);
                v = fmaf(x1, wx_s[1 * 64 + c], v);
                v = fmaf(x2, wx_s[2 * 64 + c], v);
                acc[r][q] = v;
            }
        }

#pragma unroll 4
        for (int k = 0; k < 128; k += 4) {
            const float4 w0 = *(const float4*)&wh_s[(k + 0) * 64 + tx * 4];
            const float4 w1 = *(const float4*)&wh_s[(k + 1) * 64 + tx * 4];
            const float4 w2 = *(const float4*)&wh_s[(k + 2) * 64 + tx * 4];
            const float4 w3 = *(const float4*)&wh_s[(k + 3) * 64 + tx * 4];
#pragma unroll
            for (int r = 0; r < 2; r++) {
                const float4 hv = *(const float4*)&h_s[(ty * 2 + r) * 128 + k];
                acc[r][0] = fmaf(hv.x, w0.x, acc[r][0]);
                acc[r][1] = fmaf(hv.x, w0.y, acc[r][1]);
                acc[r][2] = fmaf(hv.x, w0.z, acc[r][2]);
                acc[r][3] = fmaf(hv.x, w0.w, acc[r][3]);
                acc[r][0] = fmaf(hv.y, w1.x, acc[r][0]);
                acc[r][1] = fmaf(hv.y, w1.y, acc[r][1]);
                acc[r][2] = fmaf(hv.y, w1.z, acc[r][2]);
                acc[r][3] = fmaf(hv.y, w1.w, acc[r][3]);
                acc[r][0] = fmaf(hv.z, w2.x, acc[r][0]);
                acc[r][1] = fmaf(hv.z, w2.y, acc[r][1]);
                acc[r][2] = fmaf(hv.z, w2.z, acc[r][2]);
                acc[r][3] = fmaf(hv.z, w2.w, acc[r][3]);
                acc[r][0] = fmaf(hv.w, w3.x, acc[r][0]);
                acc[r][1] = fmaf(hv.w, w3.y, acc[r][1]);
                acc[r][2] = fmaf(hv.w, w3.z, acc[r][2]);
                acc[r][3] = fmaf(hv.w, w3.w, acc[r][3]);
            }
        }

#pragma unroll
        for (int r = 0; r < 2; r++) {
            const float c_new = creg[r] * sigm(acc[r][2] + 1.0f)
                              + sigm(acc[r][0]) * tanhf(acc[r][1]);
            const float h_new = tanhf(c_new) * sigm(acc[r][3]);
            creg[r] = c_new;
            const size_t off = ((size_t)t * BB + r0 + ty * 2 + r) * NHD + hu0 + tx;
            hs[off] = h_new;
            cs[off] = c_new;
        }

        __threadfence();
        __syncthreads();
        if (tid == 0) {
            const unsigned gen = g_gen;
            if (atomicAdd(&g_count, 1u) == NBLK_REC - 1u) {
                g_count = 0u;
                __threadfence();
                g_gen = gen + 1u;
            } else {
                while (g_gen == gen) { }
            }
        }
        __syncthreads();

        hprev = hs + (size_t)t * BB * NHD;
    }
}

// ---------------------------------------------------------------------------
// Fused readout on HMMA (mma.sync bf16, split-2 for fp32-grade precision):
//   bn = hs @ bneck_w ; pc = bn @ pc_w + pc_b ; hd = bn @ hd_w + hd_b
// One block per 128 rows, 256 threads (8 warps).
// Warp grid: wm = wid&1 (two 64-row halves), wn = wid>>1 (4 N-tiles).
// ---------------------------------------------------------------------------
// smem byte offsets (phase 1 regions die before phase 2 regions are written)
#define RA_HI   0u         // hs  [128][136] bf16  (stride 272B: conflict-free ldsm)
#define RA_LO   34816u
#define RB_HI   69632u     // bneck chunk [128][136] bf16
#define RB_LO   104448u
#define RA2_HI  0u         // bn  [128][264] bf16   (overlaps RA/RB after bn done)
#define RA2_LO  67584u
#define RB2_HI  139264u    // pc/hd weight chunk [256][72] bf16
#define RB2_LO  176128u
#define RO_SMEM 212992u
#define SA   136
#define SA2  264
#define SB2  72

__global__ void __launch_bounds__(256, 1)
readout_kernel(const float* __restrict__ hs,      // [TB,128]
               const float* __restrict__ bneck_w, // [128,256]
               const float* __restrict__ pc_w,    // [256,256]
               const float* __restrict__ pc_b,    // [256]
               const float* __restrict__ hd_w,    // [256,12]
               const float* __restrict__ hd_b,    // [12]
               float* __restrict__ bn_out,        // [TB,256]
               float* __restrict__ pc_out,        // [TB,256]
               float* __restrict__ hd_out)        // [TB,12]
{
    extern __shared__ __align__(16) char dsm[];
    const uint32_t base_u = smem_u32(dsm);
    const int tid  = threadIdx.x;
    const int wid  = tid >> 5, lane = tid & 31;
    const int wm   = wid & 1,  wn   = wid >> 1;
    const int g    = lane >> 2, tg2 = (lane & 3) * 2;
    const int lr   = lane & 15, lc8 = (lane >> 4) << 3;
    const int m0   = blockIdx.x * 128;

    // ---- stage A = hs tile, split bf16 hi/lo ----
    {
        const float* hrow = hs + (size_t)m0 * 128;
        for (int i = tid; i < 128 * 128; i += 256) {
            const int row = i >> 7, k = i & 127;
            __nv_bfloat16 hi, lo;
            split2(hrow[i], hi, lo);
            *(__nv_bfloat16*)(dsm + RA_HI + 2 * (row * SA + k)) = hi;
            *(__nv_bfloat16*)(dsm + RA_LO + 2 * (row * SA + k)) = lo;
        }
    }

    float acc[2][4][4][4];
#pragma unroll
    for (int a = 0; a < 2; a++)
#pragma unroll
        for (int b = 0; b < 4; b++)
#pragma unroll
            for (int c = 0; c < 4; c++)
#pragma unroll
                for (int d = 0; d < 4; d++) acc[a][b][c][d] = 0.0f;

    // ---- bn GEMM: two N-halves of 128, K=128 ----
#pragma unroll 1
    for (int nh = 0; nh < 2; nh++) {
        __syncthreads();   // A staged (nh=0) / previous-half MMAs done (nh=1)
        for (int i = tid; i < 128 * 128; i += 256) {
            const int k = i >> 7, n = i & 127;
            __nv_bfloat16 hi, lo;
            split2(bneck_w[(size_t)k * 256 + nh * 128 + n], hi, lo);
            *(__nv_bfloat16*)(dsm + RB_HI + 2 * (k * SA + n)) = hi;
            *(__nv_bfloat16*)(dsm + RB_LO + 2 * (k * SA + n)) = lo;
        }
        __syncthreads();

#pragma unroll
        for (int ks = 0; ks < 8; ks++) {
            const int k = ks * 16;
            uint32_t bh[4][2], bl[4][2];
#pragma unroll
            for (int p = 0; p < 2; p++) {
                const uint32_t off = 2 * ((k + lr) * SA + wn * 32 + p * 16 + lc8);
                ldsm_x4_t(bh[2*p][0], bh[2*p][1], bh[2*p+1][0], bh[2*p+1][1],
                          base_u + RB_HI + off);
                ldsm_x4_t(bl[2*p][0], bl[2*p][1], bl[2*p+1][0], bl[2*p+1][1],
                          base_u + RB_LO + off);
            }
#pragma unroll
            for (int mi = 0; mi < 4; mi++) {
                uint32_t ah[4], al[4];
                const uint32_t aoff = 2 * ((wm * 64 + mi * 16 + lr) * SA + k + lc8);
                ldsm_x4(ah[0], ah[1], ah[2], ah[3], base_u + RA_HI + aoff);
                ldsm_x4(al[0], al[1], al[2], al[3], base_u + RA_LO + aoff);
#pragma unroll
                for (int ni = 0; ni < 4; ni++) {
                    mma16816(acc[nh][mi][ni], ah, bh[ni]);
                    mma16816(acc[nh][mi][ni], ah, bl[ni]);
                    mma16816(acc[nh][mi][ni], al, bh[ni]);
                }
            }
        }
    }
    __syncthreads();   // all bn MMAs done: A/B regions dead, safe to write A2

    // ---- bn epilogue: global store + re-split into A2 (pc's A operand) ----
#pragma unroll
    for (int nh = 0; nh < 2; nh++)
#pragma unroll
    for (int mi = 0; mi < 4; mi++)
#pragma unroll
    for (int ni = 0; ni < 4; ni++) {
        const int r0  = wm * 64 + mi * 16 + g;
        const int col = nh * 128 + wn * 32 + ni * 8 + tg2;
        const float* a4 = acc[nh][mi][ni];
        *(float2*)&bn_out[(size_t)(m0 + r0) * 256 + col]     = make_float2(a4[0], a4[1]);
        *(float2*)&bn_out[(size_t)(m0 + r0 + 8) * 256 + col] = make_float2(a4[2], a4[3]);

        __nv_bfloat16 h0, l0, h1, l1;
        split2(a4[0], h0, l0); split2(a4[1], h1, l1);
        __nv_bfloat162 ph, pl;
        ph.x = h0; ph.y = h1; pl.x = l0; pl.y = l1;
        *(__nv_bfloat162*)(dsm + RA2_HI + 2 * (r0 * SA2 + col)) = ph;
        *(__nv_bfloat162*)(dsm + RA2_LO + 2 * (r0 * SA2 + col)) = pl;
        split2(a4[2], h0, l0); split2(a4[3], h1, l1);
        ph.x = h0; ph.y = h1; pl.x = l0; pl.y = l1;
        *(__nv_bfloat162*)(dsm + RA2_HI + 2 * ((r0 + 8) * SA2 + col)) = ph;
        *(__nv_bfloat162*)(dsm + RA2_LO + 2 * ((r0 + 8) * SA2 + col)) = pl;
    }

    // ---- pc (4 chunks of N=64) + hd (chunk 4, N=16 padded), K=256 ----
#pragma unroll 1
    for (int c = 0; c < 5; c++) {
        __syncthreads();   // A2 writes done (c=0) / previous chunk MMAs done
        if (c < 4) {
            for (int i = tid; i < 256 * 64; i += 256) {
                const int k = i >> 6, n = i & 63;
                __nv_bfloat16 hi, lo;
                split2(pc_w[(size_t)k * 256 + c * 64 + n], hi, lo);
                *(__nv_bfloat16*)(dsm + RB2_HI + 2 * (k * SB2 + n)) = hi;
                *(__nv_bfloat16*)(dsm + RB2_LO + 2 * (k * SB2 + n)) = lo;
            }
        } else {
            for (int i = tid; i < 256 * 16; i += 256) {
                const int k = i >> 4, n = i & 15;
                const float v = (n < 12) ? hd_w[(size_t)k * 12 + n] : 0.0f;
                __nv_bfloat16 hi, lo;
                split2(v, hi, lo);
                *(__nv_bfloat16*)(dsm + RB2_HI + 2 * (k * SB2 + n)) = hi;
                *(__nv_bfloat16*)(dsm + RB2_LO + 2 * (k * SB2 + n)) = lo;
            }
        }
        __syncthreads();

        if (c < 4) {
            float acc2[4][2][4];
#pragma unroll
            for (int a = 0; a < 4; a++)
#pragma unroll
                for (int b = 0; b < 2; b++)
#pragma unroll
                    for (int e = 0; e < 4; e++) acc2[a][b][e] = 0.0f;

#pragma unroll
            for (int ks = 0; ks < 16; ks++) {
                const int k = ks * 16;
                uint32_t bh[2][2], bl[2][2];
                const uint32_t boff = 2 * ((k + lr) * SB2 + wn * 16 + lc8);
                ldsm_x4_t(bh[0][0], bh[0][1], bh[1][0], bh[1][1], base_u + RB2_HI + boff);
                ldsm_x4_t(bl[0][0], bl[0][1], bl[1][0], bl[1][1], base_u + RB2_LO + boff);
#pragma unroll
                for (int mi = 0; mi < 4; mi++) {
                    uint32_t ah[4], al[4];
                    const uint32_t aoff = 2 * ((wm * 64 + mi * 16 + lr) * SA2 + k + lc8);
                    ldsm_x4(ah[0], ah[1], ah[2], ah[3], base_u + RA2_HI + aoff);
                    ldsm_x4(al[0], al[1], al[2], al[3], base_u + RA2_LO + aoff);
#pragma unroll
                    for (int ni = 0; ni < 2; ni++) {
                        mma16816(acc2[mi][ni], ah, bh[ni]);
                        mma16816(acc2[mi][ni], ah, bl[ni]);
                        mma16816(acc2[mi][ni], al, bh[ni]);
                    }
                }
            }
#pragma unroll
            for (int mi = 0; mi < 4; mi++)
#pragma unroll
            for (int ni = 0; ni < 2; ni++) {
                const int r0  = wm * 64 + mi * 16 + g;
                const int col = c * 64 + wn * 16 + ni * 8 + tg2;
                const float b0 = __ldg(&pc_b[col]), b1 = __ldg(&pc_b[col + 1]);
                const float* a4 = acc2[mi][ni];
                *(float2*)&pc_out[(size_t)(m0 + r0) * 256 + col] =
                    make_float2(a4[0] + b0, a4[1] + b1);
                *(float2*)&pc_out[(size_t)(m0 + r0 + 8) * 256 + col] =
                    make_float2(a4[2] + b0, a4[3] + b1);
            }
        } else if (wid < 2) {
            // hd: warps 0,1 handle M halves; N=16 (12 real)
            float acc3[4][2][4];
#pragma unroll
            for (int a = 0; a < 4; a++)
#pragma unroll
                for (int b = 0; b < 2; b++)
#pragma unroll
                    for (int e = 0; e < 4; e++) acc3[a][b][e] = 0.0f;

#pragma unroll
            for (int ks = 0; ks < 16; ks++) {
                const int k = ks * 16;
                uint32_t bh[2][2], bl[2][2];
                const uint32_t boff = 2 * ((k + lr) * SB2 + lc8);
                ldsm_x4_t(bh[0][0], bh[0][1], bh[1][0], bh[1][1], base_u + RB2_HI + boff);
                ldsm_x4_t(bl[0][0], bl[0][1], bl[1][0], bl[1][1], base_u + RB2_LO + boff);
#pragma unroll
                for (int mi = 0; mi < 4; mi++) {
                    uint32_t ah[4], al[4];
                    const uint32_t aoff = 2 * ((wid * 64 + mi * 16 + lr) * SA2 + k + lc8);
                    ldsm_x4(ah[0], ah[1], ah[2], ah[3], base_u + RA2_HI + aoff);
                    ldsm_x4(al[0], al[1], al[2], al[3], base_u + RA2_LO + aoff);
#pragma unroll
                    for (int ni = 0; ni < 2; ni++) {
                        mma16816(acc3[mi][ni], ah, bh[ni]);
                        mma16816(acc3[mi][ni], ah, bl[ni]);
                        mma16816(acc3[mi][ni], al, bh[ni]);
                    }
                }
            }
#pragma unroll
            for (int mi = 0; mi < 4; mi++)
#pragma unroll
            for (int ni = 0; ni < 2; ni++) {
                const int col = ni * 8 + tg2;
                if (col < 12) {
                    const int r0 = wid * 64 + mi * 16 + g;
                    const float b0 = __ldg(&hd_b[col]), b1 = __ldg(&hd_b[col + 1]);
                    const float* a4 = acc3[mi][ni];
                    *(float2*)&hd_out[(size_t)(m0 + r0) * 12 + col] =
                        make_float2(a4[0] + b0, a4[1] + b1);
                    *(float2*)&hd_out[(size_t)(m0 + r0 + 8) * 12 + col] =
                        make_float2(a4[2] + b0, a4[3] + b1);
                }
            }
        }
    }
}

// ---------------------------------------------------------------------------
// launch
// ---------------------------------------------------------------------------
#define LSTM_SMEM ((128 * 64 + 64 * 128 + 3 * 64 + 64 + 64 * 4) * 4)

extern "C" void kernel_launch(void* const* d_in, const int* in_sizes, int n_in,
                              void* d_out, int out_size)
{
    const float* x       = (const float*)d_in[0];
    const float* init    = (const float*)d_in[1];
    const float* rnn_w   = (const float*)d_in[2];
    const float* rnn_b   = (const float*)d_in[3];
    const float* state_w = (const float*)d_in[4];
    const float* state_b = (const float*)d_in[5];
    const float* cell_w  = (const float*)d_in[6];
    const float* cell_b  = (const float*)d_in[7];
    const float* bneck_w = (const float*)d_in[8];
    const float* pc_w    = (const float*)d_in[9];
    const float* pc_b    = (const float*)d_in[10];
    const float* hd_w    = (const float*)d_in[11];
    const float* hd_b    = (const float*)d_in[12];

    float* out = (float*)d_out;
    float* hd_out = out;
    float* pc_out = hd_out + (size_t)TB * NHDC;
    float* bn_out = pc_out + (size_t)TB * NPC;
    float* hs_out = bn_out + (size_t)TB * NBOT;
    float* cs_out = hs_out + (size_t)TB * NHD;

    float *h0p = nullptr, *c0p = nullptr;
    cudaGetSymbolAddress((void**)&h0p, g_h0);
    cudaGetSymbolAddress((void**)&c0p, g_c0);

    cudaFuncSetAttribute(lstm_kernel,
                         cudaFuncAttributeMaxDynamicSharedMemorySize, LSTM_SMEM);
    cudaFuncSetAttribute(readout_kernel,
                         cudaFuncAttributeMaxDynamicSharedMemorySize, RO_SMEM);

    // h0 / c0
    gemm_kernel<<<dim3(2, 16), 256>>>(init, state_w, state_b, h0p, BB, NHD, NIC);
    gemm_kernel<<<dim3(2, 16), 256>>>(init, cell_w,  cell_b,  c0p, BB, NHD, NIC);

    // recurrence
    lstm_kernel<<<NBLK_REC, 512, LSTM_SMEM>>>(x, rnn_w, rnn_b, hs_out, cs_out);

    // fused tensor-core readout
    readout_kernel<<<TB / 128, 256, RO_SMEM>>>(hs_out, bneck_w, pc_w, pc_b,
                                               hd_w, hd_b, bn_out, pc_out, hd_out);
}